// round 9
// baseline (speedup 1.0000x reference)
#include <cuda_runtime.h>

#define H 1024
#define S 65536
#define RPB 8                       // rows per block in GEMV (1 row per warp)
#define GEMV_GRID (S / RPB)         // 8192 blocks
#define WBLOCKS 128                 // blocks that also compute a v-slice
#define FIN_BLOCKS 256
#define FIN_TPB 256

// ---- scratch (device globals; no allocation anywhere) ----
__device__ float g_v[H];                   // v = W^T h
__device__ float g_bm[GEMV_GRID];          // per-block score max
__device__ float g_bs[GEMV_GRID];          // per-block sum of exp(s - m_b)
__device__ unsigned g_flag;                // v-ready counter (reset by k3)

// ---------------------------------------------------------------------------
// K2 (fused): v = W^T h  +  streaming GEMV  +  partial softmax.
//
// All 8192 blocks: issue 8 front-batched enc LDG.128 immediately (DRAM stream
// starts at t=0), then wait for v.
// Blocks 0..127 additionally own 8 columns of v: 8 cols x 1024 rows (32KB of W)
// read as 4 batches of 8 independent scalar LDGs, reduced in SMEM, slice
// written to g_v, then __threadfence + counter arrive.
// Everyone spins until flag==128 (blocks 0..127 are in wave 1 by bid order,
// so the producers are always resident -> no deadlock), stages v in SMEM,
// and finishes the dot products + per-block softmax.
//
// Note: the reference adds b.h to every score; a constant shift cancels in
// softmax, so it is omitted entirely.
// ---------------------------------------------------------------------------
__global__ __launch_bounds__(256) void k2_fused(const float* __restrict__ hidden,
                                                const float* __restrict__ W,
                                                const float* __restrict__ enc,
                                                float* __restrict__ out) {
    __shared__ float4 sv[H / 4];        // 4 KB staged v
    __shared__ float  hs[H];            // 4 KB staged h (W-blocks only)
    __shared__ float  red[32][9];       // rg-chunk partials, padded

    int t    = threadIdx.x;
    int warp = t >> 5;
    int lane = t & 31;
    int row  = blockIdx.x * RPB + warp;

    // ---- 1) start the enc stream NOW (front-batched, evict-first) ----
    const float4* rp = (const float4*)(enc + (size_t)row * H);
    float4 a[8];
#pragma unroll
    for (int k = 0; k < 8; k++) a[k] = __ldcs(rp + lane + 32 * k);   // MLP=8

    // ---- 2) W-duty for blocks 0..127: produce v[8b .. 8b+8) ----
    if (blockIdx.x < WBLOCKS) {
#pragma unroll
        for (int k = 0; k < 4; k++) hs[t + 256 * k] = hidden[t + 256 * k];
        __syncthreads();

        int c  = t & 7;                 // owned column within slab
        int rg = t >> 3;                // row group 0..31, rows rg + 32k
        const float* Wp = W + (size_t)rg * H + blockIdx.x * 8 + c;

        float acc = 0.f;
#pragma unroll
        for (int kb = 0; kb < 32; kb += 8) {
            float w0 = Wp[(size_t)(kb + 0) * 32 * H];
            float w1 = Wp[(size_t)(kb + 1) * 32 * H];
            float w2 = Wp[(size_t)(kb + 2) * 32 * H];
            float w3 = Wp[(size_t)(kb + 3) * 32 * H];
            float w4 = Wp[(size_t)(kb + 4) * 32 * H];
            float w5 = Wp[(size_t)(kb + 5) * 32 * H];
            float w6 = Wp[(size_t)(kb + 6) * 32 * H];
            float w7 = Wp[(size_t)(kb + 7) * 32 * H];
            acc = fmaf(w0, hs[rg + (kb + 0) * 32], acc);
            acc = fmaf(w1, hs[rg + (kb + 1) * 32], acc);
            acc = fmaf(w2, hs[rg + (kb + 2) * 32], acc);
            acc = fmaf(w3, hs[rg + (kb + 3) * 32], acc);
            acc = fmaf(w4, hs[rg + (kb + 4) * 32], acc);
            acc = fmaf(w5, hs[rg + (kb + 5) * 32], acc);
            acc = fmaf(w6, hs[rg + (kb + 6) * 32], acc);
            acc = fmaf(w7, hs[rg + (kb + 7) * 32], acc);
        }
        red[rg][c] = acc;
        __syncthreads();
#pragma unroll
        for (int o = 16; o; o >>= 1) {
            if (rg < o) red[rg][c] += red[rg + o][c];
            __syncthreads();
        }
        if (t < 8) g_v[blockIdx.x * 8 + t] = red[0][t];
        __threadfence();
        if (t == 0) atomicAdd(&g_flag, 1u);
    }

    // ---- 3) wait for v, stage it ----
    if (t == 0) {
        volatile unsigned* f = &g_flag;
        while (*f < WBLOCKS) { }
    }
    __syncthreads();
    __threadfence();                     // order v reads after flag observation
    sv[t] = ((const float4*)g_v)[t];
    __syncthreads();

    // ---- 4) dot products + per-block partial softmax ----
    float acc = 0.f;
#pragma unroll
    for (int k = 0; k < 8; k++) {
        float4 vv = sv[lane + 32 * k];
        acc = fmaf(a[k].x, vv.x, acc);
        acc = fmaf(a[k].y, vv.y, acc);
        acc = fmaf(a[k].z, vv.z, acc);
        acc = fmaf(a[k].w, vv.w, acc);
    }
#pragma unroll
    for (int o = 16; o; o >>= 1) acc += __shfl_xor_sync(0xFFFFFFFFu, acc, o);

    __shared__ float ws[RPB];
    if (lane == 0) ws[warp] = acc;
    __syncthreads();

    if (t == 0) {
        float mb = ws[0];
#pragma unroll
        for (int i = 1; i < RPB; i++) mb = fmaxf(mb, ws[i]);
        float sm = 0.f;
#pragma unroll
        for (int i = 0; i < RPB; i++) {
            float e = expf(ws[i] - mb);
            sm += e;
            out[blockIdx.x * RPB + i] = e;
        }
        g_bm[blockIdx.x] = mb;
        g_bs[blockIdx.x] = sm;
    }
}

// ---------------------------------------------------------------------------
// K3: finalize. Each block redundantly reduces the 8192 (m_b, sum_b) pairs
// (L2-resident, fixed order -> deterministic), then rescales its 256 outputs:
//   out[i] *= exp(m_b(i) - gmax) / total
// Also resets g_flag for the next graph replay.
// ---------------------------------------------------------------------------
__global__ __launch_bounds__(FIN_TPB) void k3_finalize(float* __restrict__ out) {
    __shared__ float s[FIN_TPB];
    int t = threadIdx.x;

    if (blockIdx.x == 0 && t == 0) g_flag = 0;   // reset for replay

    float m = -3.4e38f;
#pragma unroll
    for (int k = 0; k < GEMV_GRID / FIN_TPB; k++)
        m = fmaxf(m, g_bm[t + FIN_TPB * k]);
    s[t] = m;
    __syncthreads();
    for (int o = FIN_TPB / 2; o; o >>= 1) {
        if (t < o) s[t] = fmaxf(s[t], s[t + o]);
        __syncthreads();
    }
    float gmax = s[0];
    __syncthreads();

    float sm = 0.f;
#pragma unroll
    for (int k = 0; k < GEMV_GRID / FIN_TPB; k++) {
        int idx = t + FIN_TPB * k;
        sm += g_bs[idx] * expf(g_bm[idx] - gmax);
    }
    s[t] = sm;
    __syncthreads();
    for (int o = FIN_TPB / 2; o; o >>= 1) {
        if (t < o) s[t] += s[t + o];
        __syncthreads();
    }
    float inv = 1.0f / s[0];

    int i = blockIdx.x * FIN_TPB + t;
    out[i] = out[i] * expf(g_bm[i >> 3] - gmax) * inv;
}

extern "C" void kernel_launch(void* const* d_in, const int* in_sizes, int n_in,
                              void* d_out, int out_size) {
    const float* hidden = (const float*)d_in[0];   // [1024]
    const float* enc    = (const float*)d_in[1];   // [65536, 1024]
    const float* W      = (const float*)d_in[2];   // [1024, 1024]
    float* out = (float*)d_out;                    // [65536]

    k2_fused<<<GEMV_GRID, 256>>>(hidden, W, enc, out);
    k3_finalize<<<FIN_BLOCKS, FIN_TPB>>>(out);
}

// round 11
// speedup vs baseline: 1.1583x; 1.1583x over previous
#include <cuda_runtime.h>

#define H 1024
#define S 65536
#define RPB 8                       // rows per block in GEMV (1 row per warp)
#define GEMV_GRID (S / RPB)         // 8192 blocks

// ---- scratch (device globals; no allocation anywhere) ----
__device__ float g_v[H];                   // v = W^T h
__device__ float g_bm[GEMV_GRID];          // per-block score max
__device__ float g_bs[GEMV_GRID];          // per-block sum of exp(s - m_b)
__device__ float g_gmax;                   // global max
__device__ float g_inv;                    // 1 / total

// ---------------------------------------------------------------------------
// K1: v = W^T h. 128 blocks x 256 threads; block b owns columns 8b..8b+7
// (32 KB slab of W). Thread (c = t&7, rg = t>>3): column 8b+c, rows rg+32k,
// 4 batches of 8 independent scalar LDGs (MLP=8, tiny reg footprint).
// Each warp load covers 4 fully-consumed 32B sectors. SMEM tree over rg.
// b.h is omitted: a constant shift cancels in softmax.
// ---------------------------------------------------------------------------
__global__ __launch_bounds__(256) void k1_prep(const float* __restrict__ hidden,
                                               const float* __restrict__ W) {
    __shared__ float hs[H];
    __shared__ float red[32][9];            // padded
    int t = threadIdx.x;

#pragma unroll
    for (int k = 0; k < 4; k++) hs[t + 256 * k] = hidden[t + 256 * k];
    __syncthreads();

    int c  = t & 7;                         // owned column within slab
    int rg = t >> 3;                        // row group 0..31 (rows rg + 32k)
    const float* Wp = W + (size_t)rg * H + blockIdx.x * 8 + c;

    float acc = 0.f;
#pragma unroll
    for (int kb = 0; kb < 32; kb += 8) {
        float w0 = Wp[(size_t)(kb + 0) * 32 * H];
        float w1 = Wp[(size_t)(kb + 1) * 32 * H];
        float w2 = Wp[(size_t)(kb + 2) * 32 * H];
        float w3 = Wp[(size_t)(kb + 3) * 32 * H];
        float w4 = Wp[(size_t)(kb + 4) * 32 * H];
        float w5 = Wp[(size_t)(kb + 5) * 32 * H];
        float w6 = Wp[(size_t)(kb + 6) * 32 * H];
        float w7 = Wp[(size_t)(kb + 7) * 32 * H];
        acc = fmaf(w0, hs[rg + (kb + 0) * 32], acc);
        acc = fmaf(w1, hs[rg + (kb + 1) * 32], acc);
        acc = fmaf(w2, hs[rg + (kb + 2) * 32], acc);
        acc = fmaf(w3, hs[rg + (kb + 3) * 32], acc);
        acc = fmaf(w4, hs[rg + (kb + 4) * 32], acc);
        acc = fmaf(w5, hs[rg + (kb + 5) * 32], acc);
        acc = fmaf(w6, hs[rg + (kb + 6) * 32], acc);
        acc = fmaf(w7, hs[rg + (kb + 7) * 32], acc);
    }
    red[rg][c] = acc;
    __syncthreads();
#pragma unroll
    for (int o = 16; o; o >>= 1) {
        if (rg < o) red[rg][c] += red[rg + o][c];
        __syncthreads();
    }
    if (t < 8) g_v[blockIdx.x * 8 + t] = red[0][t];
}

// ---------------------------------------------------------------------------
// K2: streaming GEMV + partial softmax. (Unchanged: measured ~7.9 TB/s.)
// 1 warp per row, 8x front-batched LDG.128 (evict-first), v staged in shared.
// Per block: out[row] = exp(score - m_b); store (m_b, sum_b).
// ---------------------------------------------------------------------------
__global__ __launch_bounds__(256) void k2_gemv(const float* __restrict__ enc,
                                               float* __restrict__ out) {
    __shared__ float4 sv[H / 4];        // 4 KB
    sv[threadIdx.x] = ((const float4*)g_v)[threadIdx.x];
    __syncthreads();

    int warp = threadIdx.x >> 5;
    int lane = threadIdx.x & 31;
    int row  = blockIdx.x * RPB + warp;
    const float4* rp = (const float4*)(enc + (size_t)row * H);

    float4 a[8];
#pragma unroll
    for (int k = 0; k < 8; k++) a[k] = __ldcs(rp + lane + 32 * k);   // MLP=8

    float acc = 0.f;
#pragma unroll
    for (int k = 0; k < 8; k++) {
        float4 vv = sv[lane + 32 * k];
        acc = fmaf(a[k].x, vv.x, acc);
        acc = fmaf(a[k].y, vv.y, acc);
        acc = fmaf(a[k].z, vv.z, acc);
        acc = fmaf(a[k].w, vv.w, acc);
    }
#pragma unroll
    for (int o = 16; o; o >>= 1) acc += __shfl_xor_sync(0xFFFFFFFFu, acc, o);

    __shared__ float ws[RPB];
    if (lane == 0) ws[warp] = acc;
    __syncthreads();

    if (threadIdx.x == 0) {
        float mb = ws[0];
#pragma unroll
        for (int i = 1; i < RPB; i++) mb = fmaxf(mb, ws[i]);
        float sm = 0.f;
#pragma unroll
        for (int i = 0; i < RPB; i++) {
            float e = expf(ws[i] - mb);
            sm += e;
            out[blockIdx.x * RPB + i] = e;
        }
        g_bm[blockIdx.x] = mb;
        g_bs[blockIdx.x] = sm;
    }
}

// ---------------------------------------------------------------------------
// K3a: ONE 1024-thread block reduces the 8192 (m_b, sum_b) pairs (L2-resident,
// fixed order -> deterministic) to g_gmax and g_inv. Done once, not 256x.
// ---------------------------------------------------------------------------
__global__ __launch_bounds__(1024) void k3a_reduce() {
    __shared__ float s[1024];
    int t = threadIdx.x;

    float m = -3.4e38f;
#pragma unroll
    for (int k = 0; k < GEMV_GRID / 1024; k++)
        m = fmaxf(m, g_bm[t + 1024 * k]);
    s[t] = m;
    __syncthreads();
    for (int o = 512; o; o >>= 1) {
        if (t < o) s[t] = fmaxf(s[t], s[t + o]);
        __syncthreads();
    }
    float gmax = s[0];
    __syncthreads();

    float sm = 0.f;
#pragma unroll
    for (int k = 0; k < GEMV_GRID / 1024; k++) {
        int idx = t + 1024 * k;
        sm += g_bs[idx] * expf(g_bm[idx] - gmax);
    }
    s[t] = sm;
    __syncthreads();
    for (int o = 512; o; o >>= 1) {
        if (t < o) s[t] += s[t + o];
        __syncthreads();
    }
    if (t == 0) { g_gmax = gmax; g_inv = 1.0f / s[0]; }
}

// ---------------------------------------------------------------------------
// K3b: scale pass, float4-vectorized. 4 consecutive outputs share one g_bm
// entry (4 | 8), so one expf per float4.
// ---------------------------------------------------------------------------
__global__ __launch_bounds__(256) void k3b_scale(float* __restrict__ out) {
    int i4 = blockIdx.x * 256 + threadIdx.x;      // float4 index
    float f = expf(g_bm[i4 >> 1] - g_gmax) * g_inv;  // (4*i4)>>3 == i4>>1
    float4 v = ((float4*)out)[i4];
    v.x *= f; v.y *= f; v.z *= f; v.w *= f;
    ((float4*)out)[i4] = v;
}

extern "C" void kernel_launch(void* const* d_in, const int* in_sizes, int n_in,
                              void* d_out, int out_size) {
    const float* hidden = (const float*)d_in[0];   // [1024]
    const float* enc    = (const float*)d_in[1];   // [65536, 1024]
    const float* W      = (const float*)d_in[2];   // [1024, 1024]
    float* out = (float*)d_out;                    // [65536]

    k1_prep<<<128, 256>>>(hidden, W);
    k2_gemv<<<GEMV_GRID, 256>>>(enc, out);
    k3a_reduce<<<1, 1024>>>();
    k3b_scale<<<S / 4 / 256, 256>>>(out);
}